// round 2
// baseline (speedup 1.0000x reference)
#include <cuda_runtime.h>
#include <cuda_bf16.h>
#include <math.h>

// ---------------- problem constants ----------------
#define T_DIM   2048
#define HID     5120
#define QLR     1536
#define KVLR    512
#define NOPE    128
#define ROPE_D  64
#define VDIM    128
#define H_HEADS 32
#define QKD     192            // NOPE + ROPE
#define DQK     576            // KVLR + ROPE  (q_input / k_input dim)
#define ATTN_SCALE 0.07216878364870323f   // 192^-0.5
#define RMS_EPS 1e-6f

// ---------------- scratch (static device globals; allocation-free) ----------
__device__ float g_qa    [T_DIM * QLR];                 // hidden @ w_q_a
__device__ float g_qan   [T_DIM * QLR];                 // rmsnorm(g_qa)
__device__ float g_qproj [T_DIM * H_HEADS * QKD];       // q (pre-split)
__device__ float g_latent[T_DIM * DQK];                 // hidden @ w_kv_a
__device__ float g_kin   [T_DIM * DQK];                 // [v_input | roped k_pe]
__device__ float g_cs    [T_DIM * ROPE_D];              // per-t cos[32], sin[32]
__device__ float g_qin   [37748736];                    // [H][T][576]
__device__ float g_scores[134217728];                   // [H][T][T]
__device__ float g_ctx   [33554432];                    // [H][T][512]
__device__ float g_attn  [T_DIM * H_HEADS * VDIM];      // [T][H*128]

// ---------------- generic fp32 tiled GEMM ----------------------------------
// C[M,N] = alpha * A[M,K] (@ B or @ B^T), row-major, optional batching via
// blockIdx.z with element strides sA/sB/sC.
// CAUSAL==1: (scores, requires TRANSB) skip blocks strictly above diagonal.
// CAUSAL==2: (ctx) clamp K to the causal tile limit m0+128.
// Assumes: M % 128 == 0, K % 8 == 0, lda/ldb/ldc % 4 == 0, pointers 16B-aligned.
template <bool TRANSB, int CAUSAL>
__global__ __launch_bounds__(256, 2)
void sgemm(const float* __restrict__ A, const float* __restrict__ B,
           float* __restrict__ C,
           int M, int N, int K, int lda, int ldb, int ldc,
           long long sA, long long sB, long long sC, float alpha)
{
    const int m0 = blockIdx.y * 128;
    const int n0 = blockIdx.x * 128;
    if (CAUSAL == 1 && n0 > m0 + 127) return;   // fully masked tile

    A += (long long)blockIdx.z * sA;
    B += (long long)blockIdx.z * sB;
    C += (long long)blockIdx.z * sC;

    const int Keff = (CAUSAL == 2) ? min(K, m0 + 128) : K;

    __shared__ float As[8][128];
    __shared__ float Bs[8][128];

    const int tid  = threadIdx.x;
    const int trow = tid >> 4;      // 0..15
    const int tcol = tid & 15;      // 0..15

    float acc[8][8];
#pragma unroll
    for (int i = 0; i < 8; i++)
#pragma unroll
        for (int j = 0; j < 8; j++) acc[i][j] = 0.f;

    const int arow = tid >> 1;          // 0..127
    const int acol = (tid & 1) * 4;     // 0 or 4

    for (int k0 = 0; k0 < Keff; k0 += 8) {
        // ---- A tile: 128 x 8, stored transposed As[k][m]
        {
            float4 a4 = *(const float4*)(A + (long long)(m0 + arow) * lda + k0 + acol);
            As[acol + 0][arow] = a4.x;
            As[acol + 1][arow] = a4.y;
            As[acol + 2][arow] = a4.z;
            As[acol + 3][arow] = a4.w;
        }
        // ---- B tile
        if (TRANSB) {
            const int brow = tid >> 1;          // n 0..127
            const int bcol = (tid & 1) * 4;     // k
            float4 b4 = make_float4(0.f, 0.f, 0.f, 0.f);
            if (n0 + brow < N)
                b4 = *(const float4*)(B + (long long)(n0 + brow) * ldb + k0 + bcol);
            Bs[bcol + 0][brow] = b4.x;
            Bs[bcol + 1][brow] = b4.y;
            Bs[bcol + 2][brow] = b4.z;
            Bs[bcol + 3][brow] = b4.w;
        } else {
            const int bk = tid >> 5;            // 0..7
            const int bn = (tid & 31) * 4;      // 0..124
            const float* bp = B + (long long)(k0 + bk) * ldb + n0 + bn;
            float4 b4;
            if (n0 + bn + 3 < N) {
                b4 = *(const float4*)bp;
            } else {
                b4.x = (n0 + bn + 0 < N) ? bp[0] : 0.f;
                b4.y = (n0 + bn + 1 < N) ? bp[1] : 0.f;
                b4.z = (n0 + bn + 2 < N) ? bp[2] : 0.f;
                b4.w = (n0 + bn + 3 < N) ? bp[3] : 0.f;
            }
            *(float4*)&Bs[bk][bn] = b4;
        }
        __syncthreads();

#pragma unroll
        for (int kk = 0; kk < 8; kk++) {
            float a[8], b[8];
            *(float4*)&a[0] = *(const float4*)&As[kk][trow * 8];
            *(float4*)&a[4] = *(const float4*)&As[kk][trow * 8 + 4];
            *(float4*)&b[0] = *(const float4*)&Bs[kk][tcol * 8];
            *(float4*)&b[4] = *(const float4*)&Bs[kk][tcol * 8 + 4];
#pragma unroll
            for (int i = 0; i < 8; i++)
#pragma unroll
                for (int j = 0; j < 8; j++)
                    acc[i][j] += a[i] * b[j];
        }
        __syncthreads();
    }

    // ---- epilogue
#pragma unroll
    for (int i = 0; i < 8; i++) {
        const int m = m0 + trow * 8 + i;
        float* cp = C + (long long)m * ldc + n0 + tcol * 8;
        if (n0 + tcol * 8 + 7 < N) {
            float4 c0 = make_float4(acc[i][0] * alpha, acc[i][1] * alpha,
                                    acc[i][2] * alpha, acc[i][3] * alpha);
            float4 c1 = make_float4(acc[i][4] * alpha, acc[i][5] * alpha,
                                    acc[i][6] * alpha, acc[i][7] * alpha);
            *(float4*)cp       = c0;
            *((float4*)cp + 1) = c1;
        } else {
#pragma unroll
            for (int j = 0; j < 8; j++)
                if (n0 + tcol * 8 + j < N) cp[j] = acc[i][j] * alpha;
        }
    }
}

// ---------------- RMSNorm (one block per row) -------------------------------
__global__ void rmsnorm_kernel(const float* __restrict__ x,
                               const float* __restrict__ w,
                               float* __restrict__ y, int D)
{
    const int row = blockIdx.x;
    const float* xr = x + (long long)row * D;
    float* yr       = y + (long long)row * D;

    float ss = 0.f;
    for (int i = threadIdx.x; i < D; i += 256) { float v = xr[i]; ss += v * v; }
    __shared__ float red[256];
    red[threadIdx.x] = ss;
    __syncthreads();
    for (int s = 128; s > 0; s >>= 1) {
        if (threadIdx.x < s) red[threadIdx.x] += red[threadIdx.x + s];
        __syncthreads();
    }
    const float r = rsqrtf(red[0] / (float)D + RMS_EPS);
    for (int i = threadIdx.x; i < D; i += 256) yr[i] = xr[i] * r * w[i];
}

// ---------------- build k_input: rmsnorm(latent[:512]) + rope(k_pe) ---------
// positions may arrive as int32 or int64 depending on harness dtype handling.
// Sniff on-device: int64 little-endian arange has p32[1]==0 (high word of
// element 0); int32 arange has p32[1]==1. Deterministic for the given inputs.
__global__ void build_k_kernel(const float* __restrict__ latent,
                               const float* __restrict__ w,
                               const int* __restrict__ pos32,
                               float* __restrict__ kin,
                               float* __restrict__ cs)
{
    const int t = blockIdx.x;
    const float* lr = latent + (long long)t * DQK;
    float* kr       = kin    + (long long)t * DQK;

    float ss = 0.f;
    for (int i = threadIdx.x; i < KVLR; i += 256) { float v = lr[i]; ss += v * v; }
    __shared__ float red[256];
    red[threadIdx.x] = ss;
    __syncthreads();
    for (int s = 128; s > 0; s >>= 1) {
        if (threadIdx.x < s) red[threadIdx.x] += red[threadIdx.x + s];
        __syncthreads();
    }
    const float r = rsqrtf(red[0] / (float)KVLR + RMS_EPS);
    for (int i = threadIdx.x; i < KVLR; i += 256) kr[i] = lr[i] * r * w[i];

    if (threadIdx.x < 32) {
        const int j = threadIdx.x;
        const bool is64 = (pos32[1] == 0);   // int64 layout: high word of pos[0]
        const long long p = is64 ? ((const long long*)pos32)[t]
                                 : (long long)pos32[t];
        const double inv = pow(10000.0, -(double)(2 * j) / (double)ROPE_D);
        const double ang = (double)p * inv;
        const float c = (float)cos(ang);
        const float s = (float)sin(ang);
        cs[t * ROPE_D + j]      = c;
        cs[t * ROPE_D + 32 + j] = s;
        const float x1 = lr[KVLR + 2 * j];
        const float x2 = lr[KVLR + 2 * j + 1];
        kr[KVLR + 2 * j]     = x1 * c - x2 * s;
        kr[KVLR + 2 * j + 1] = x2 * c + x1 * s;
    }
}

// ---------------- rope q_pe into q_input[.., 512:576] -----------------------
__global__ void rope_q_kernel(const float* __restrict__ q,
                              const float* __restrict__ cs,
                              float* __restrict__ qin)
{
    const int t = blockIdx.x;
    const int h = blockIdx.y * blockDim.y + threadIdx.y;
    const int j = threadIdx.x;   // 0..31

    const float c = cs[t * ROPE_D + j];
    const float s = cs[t * ROPE_D + 32 + j];
    const float* qr = q + (long long)t * (H_HEADS * QKD) + h * QKD + NOPE;
    const float x1 = qr[2 * j];
    const float x2 = qr[2 * j + 1];
    float* o = qin + ((long long)h * T_DIM + t) * DQK + KVLR;
    o[2 * j]     = x1 * c - x2 * s;
    o[2 * j + 1] = x2 * c + x1 * s;
}

// ---------------- causal softmax (one block per (t,h) row) ------------------
__global__ void softmax_kernel(float* __restrict__ scores)
{
    const int t = blockIdx.x;
    const int h = blockIdx.y;
    float* row = scores + ((long long)h * T_DIM + t) * T_DIM;
    const int len = t + 1;

    __shared__ float red[256];

    float mx = -1e30f;
    for (int i = threadIdx.x; i < len; i += 256) mx = fmaxf(mx, row[i]);
    red[threadIdx.x] = mx;
    __syncthreads();
    for (int s = 128; s > 0; s >>= 1) {
        if (threadIdx.x < s) red[threadIdx.x] = fmaxf(red[threadIdx.x], red[threadIdx.x + s]);
        __syncthreads();
    }
    mx = red[0];
    __syncthreads();

    float sum = 0.f;
    for (int i = threadIdx.x; i < len; i += 256) sum += expf(row[i] - mx);
    red[threadIdx.x] = sum;
    __syncthreads();
    for (int s = 128; s > 0; s >>= 1) {
        if (threadIdx.x < s) red[threadIdx.x] += red[threadIdx.x + s];
        __syncthreads();
    }
    const float inv = 1.f / red[0];

    for (int i = threadIdx.x; i < len; i += 256) row[i] = expf(row[i] - mx) * inv;

    // zero-fill only up to the 128-aligned tile boundary — ctx GEMM clamps K there
    const int zend = min(T_DIM, ((t >> 7) + 1) << 7);
    for (int i = len + threadIdx.x; i < zend; i += 256) row[i] = 0.f;
}

// ---------------- launch ----------------------------------------------------
extern "C" void kernel_launch(void* const* d_in, const int* in_sizes, int n_in,
                              void* d_out, int out_size)
{
    const float*     hidden     = (const float*)d_in[0];
    const int*       positions  = (const int*)d_in[1];   // int32 or int64 bits — sniffed on device
    const float*     w_q_a      = (const float*)d_in[2];
    const float*     q_a_ln_w   = (const float*)d_in[3];
    const float*     w_q_b      = (const float*)d_in[4];
    const float*     w_kv_a     = (const float*)d_in[5];
    const float*     kv_a_ln_w  = (const float*)d_in[6];
    const float*     w_kc       = (const float*)d_in[7];
    const float*     w_vc       = (const float*)d_in[8];
    const float*     w_o        = (const float*)d_in[9];
    float*           out        = (float*)d_out;

    float *qa, *qan, *qproj, *latent, *kin, *cs, *qin, *scores, *ctx, *attn;
    cudaGetSymbolAddress((void**)&qa,     g_qa);
    cudaGetSymbolAddress((void**)&qan,    g_qan);
    cudaGetSymbolAddress((void**)&qproj,  g_qproj);
    cudaGetSymbolAddress((void**)&latent, g_latent);
    cudaGetSymbolAddress((void**)&kin,    g_kin);
    cudaGetSymbolAddress((void**)&cs,     g_cs);
    cudaGetSymbolAddress((void**)&qin,    g_qin);
    cudaGetSymbolAddress((void**)&scores, g_scores);
    cudaGetSymbolAddress((void**)&ctx,    g_ctx);
    cudaGetSymbolAddress((void**)&attn,   g_attn);

    // 1. q_a = hidden @ w_q_a                        [2048,5120]x[5120,1536]
    sgemm<false, 0><<<dim3(QLR / 128, T_DIM / 128, 1), 256>>>(
        hidden, w_q_a, qa, T_DIM, QLR, HID, HID, QLR, QLR, 0, 0, 0, 1.f);

    // 2. q_a_norm = rmsnorm(q_a)
    rmsnorm_kernel<<<T_DIM, 256>>>(qa, q_a_ln_w, qan, QLR);

    // 3. q = q_a_norm @ w_q_b                        [2048,1536]x[1536,6144]
    sgemm<false, 0><<<dim3(48, T_DIM / 128, 1), 256>>>(
        qan, w_q_b, qproj, T_DIM, H_HEADS * QKD, QLR,
        QLR, H_HEADS * QKD, H_HEADS * QKD, 0, 0, 0, 1.f);

    // 4. latent = hidden @ w_kv_a                    [2048,5120]x[5120,576]
    sgemm<false, 0><<<dim3((DQK + 127) / 128, T_DIM / 128, 1), 256>>>(
        hidden, w_kv_a, latent, T_DIM, DQK, HID, HID, DQK, DQK, 0, 0, 0, 1.f);

    // 5. k_input = [rmsnorm(latent[:,:512]) | rope(latent[:,512:])]; cos/sin table
    build_k_kernel<<<T_DIM, 256>>>(latent, kv_a_ln_w, positions, kin, cs);

    // 6. q_input[h][:, :512] = q_nope_h @ w_kc[h]    batched [2048,128]x[128,512]
    sgemm<false, 0><<<dim3(KVLR / 128, T_DIM / 128, H_HEADS), 256>>>(
        qproj, w_kc, qin, T_DIM, KVLR, NOPE,
        H_HEADS * QKD, KVLR, DQK,
        (long long)QKD, (long long)NOPE * KVLR, (long long)T_DIM * DQK, 1.f);

    // 7. q_input[h][:, 512:576] = rope(q_pe)
    rope_q_kernel<<<dim3(T_DIM, H_HEADS / 8), dim3(32, 8)>>>(qproj, cs, qin);

    // 8. scores[h] = SCALE * q_input[h] @ k_input^T  (causal block-skip)
    sgemm<true, 1><<<dim3(T_DIM / 128, T_DIM / 128, H_HEADS), 256>>>(
        qin, kin, scores, T_DIM, T_DIM, DQK, DQK, DQK, T_DIM,
        (long long)T_DIM * DQK, 0, (long long)T_DIM * T_DIM, ATTN_SCALE);

    // 9. causal softmax (zero-fills up to tile boundary)
    softmax_kernel<<<dim3(T_DIM, H_HEADS), 256>>>(scores);

    // 10. ctx[h] = probs[h] @ v_input                (K clamped causally)
    sgemm<false, 2><<<dim3(KVLR / 128, T_DIM / 128, H_HEADS), 256>>>(
        scores, kin, ctx, T_DIM, KVLR, T_DIM, T_DIM, DQK, KVLR,
        (long long)T_DIM * T_DIM, 0, (long long)T_DIM * KVLR, 1.f);

    // 11. attn[:, h*128:(h+1)*128] = ctx[h] @ w_vc[h]  batched [2048,512]x[512,128]
    sgemm<false, 0><<<dim3(1, T_DIM / 128, H_HEADS), 256>>>(
        ctx, w_vc, attn, T_DIM, VDIM, KVLR, KVLR, VDIM, H_HEADS * VDIM,
        (long long)T_DIM * KVLR, (long long)KVLR * VDIM, (long long)VDIM, 1.f);

    // 12. out = attn @ w_o                           [2048,4096]x[4096,5120]
    sgemm<false, 0><<<dim3(HID / 128, T_DIM / 128, 1), 256>>>(
        attn, w_o, out, T_DIM, HID, H_HEADS * VDIM,
        H_HEADS * VDIM, HID, HID, 0, 0, 0, 1.f);
}